// round 7
// baseline (speedup 1.0000x reference)
#include <cuda_runtime.h>
#include <cuda_fp16.h>
#include <math.h>
#include <stdint.h>

#define BB 4
#define NN 4096
#define DD 256
#define MTOT (BB*NN)          // 16384
#define KAUG 768              // 3 x 256 split-fp16 augmented K (projections)
#define SCALE_F 0.17677669529663689f
#define BAND 0.008f

// ---------------- static device scratch ------------------------------------
__device__ __half g_Aaug[(size_t)MTOT*KAUG];   // xaug, later reused for att-aug
__device__ __half g_Baug[(size_t)MTOT*KAUG];   // yaug
__device__ __half g_Kh  [(size_t)MTOT*DD];     // K rounded to fp16 (cheap pass)
__device__ float  g_Q [(size_t)MTOT*DD];
__device__ float  g_K [(size_t)MTOT*DD];
__device__ float  g_V [(size_t)MTOT*DD];
__device__ float  g_att[(size_t)MTOT*DD];
__device__ __half g_Wt[4][(size_t)DD*KAUG];    // weights transposed + split (B-style)
__device__ int    g_cnt;
__device__ int    g_list[MTOT];

// ---------------- PTX helpers ----------------------------------------------
__device__ __forceinline__ uint32_t smem_u32(const void* p){
    uint32_t a;
    asm("{ .reg .u64 t; cvta.to.shared.u64 t, %1; cvt.u32.u64 %0, t; }" : "=r"(a) : "l"(p));
    return a;
}
#define CP16(dst, src) \
    asm volatile("cp.async.cg.shared.global [%0], [%1], 16;" :: "r"(dst), "l"(src) : "memory")
#define CPC()  asm volatile("cp.async.commit_group;" ::: "memory")
#define CPW0() asm volatile("cp.async.wait_group 0;" ::: "memory")

__device__ __forceinline__ void ldsm4(uint32_t a, uint32_t& r0, uint32_t& r1,
                                      uint32_t& r2, uint32_t& r3){
    asm volatile("ldmatrix.sync.aligned.m8n8.x4.shared.b16 {%0,%1,%2,%3}, [%4];"
        : "=r"(r0), "=r"(r1), "=r"(r2), "=r"(r3) : "r"(a));
}
__device__ __forceinline__ void mma16816(float* c,
        uint32_t a0, uint32_t a1, uint32_t a2, uint32_t a3,
        uint32_t b0, uint32_t b1){
    asm volatile("mma.sync.aligned.m16n8k16.row.col.f32.f16.f16.f32 "
        "{%0,%1,%2,%3}, {%4,%5,%6,%7}, {%8,%9}, {%0,%1,%2,%3};"
        : "+f"(c[0]), "+f"(c[1]), "+f"(c[2]), "+f"(c[3])
        : "r"(a0), "r"(a1), "r"(a2), "r"(a3), "r"(b0), "r"(b1));
}

// ---------------- prep kernels ----------------------------------------------
// A-side augmentation: [h | h | l]
__global__ void prep_aug(const float* __restrict__ src, __half* __restrict__ dst)
{
    const size_t total = (size_t)MTOT * 64;   // float4 count
    for (size_t i = (size_t)blockIdx.x*blockDim.x + threadIdx.x; i < total;
         i += (size_t)gridDim.x*blockDim.x) {
        size_t row = i >> 6; int c4 = (int)(i & 63);
        float4 v = ((const float4*)src)[i];
        __half h0=__float2half_rn(v.x), h1=__float2half_rn(v.y);
        __half h2=__float2half_rn(v.z), h3=__float2half_rn(v.w);
        __half2 H01=__halves2half2(h0,h1), H23=__halves2half2(h2,h3);
        __half2 L01=__halves2half2(__float2half_rn(v.x-__half2float(h0)),
                                   __float2half_rn(v.y-__half2float(h1)));
        __half2 L23=__halves2half2(__float2half_rn(v.z-__half2float(h2)),
                                   __float2half_rn(v.w-__half2float(h3)));
        __half* base = dst + row*KAUG + c4*4;
        ((__half2*)base)[0] = H01; ((__half2*)base)[1] = H23;
        ((__half2*)(base+256))[0] = H01; ((__half2*)(base+256))[1] = H23;
        ((__half2*)(base+512))[0] = L01; ((__half2*)(base+512))[1] = L23;
    }
}

// plain fp32 -> fp16 round (cheap-pass K)
__global__ void prep_h(const float* __restrict__ src, __half* __restrict__ dst)
{
    const size_t total = (size_t)MTOT * 64;
    for (size_t i = (size_t)blockIdx.x*blockDim.x + threadIdx.x; i < total;
         i += (size_t)gridDim.x*blockDim.x) {
        float4 v = ((const float4*)src)[i];
        __half2 a = __halves2half2(__float2half_rn(v.x), __float2half_rn(v.y));
        __half2 b = __halves2half2(__float2half_rn(v.z), __float2half_rn(v.w));
        ((__half2*)dst)[i*2]   = a;
        ((__half2*)dst)[i*2+1] = b;
    }
}

// all 4 weights: W[256k x 256n] fp32 -> Wt[256n x 768k] half, B-style split
__global__ void prep_wt4(const float* __restrict__ W0, const float* __restrict__ W1,
                         const float* __restrict__ W2, const float* __restrict__ W3,
                         __half* __restrict__ Wt)
{
    const float* W = (blockIdx.y==0)?W0:(blockIdx.y==1)?W1:(blockIdx.y==2)?W2:W3;
    __half* dst = Wt + (size_t)blockIdx.y * DD * KAUG;
    int k = blockIdx.x;
    int n = threadIdx.x;
    float v = W[(size_t)k*DD + n];
    __half h = __float2half_rn(v);
    __half l = __float2half_rn(v - __half2float(h));
    dst[(size_t)n*KAUG + k]       = h;
    dst[(size_t)n*KAUG + 256 + k] = l;
    dst[(size_t)n*KAUG + 512 + k] = h;
}

// ---------------- HMMA GEMM: C[M,256] = Aaug[M,768] . Wt[256,768]^T (+bias) --
template<bool BIAS>
__global__ __launch_bounds__(256) void hgemm(const __half* __restrict__ A,
                                             const __half* __restrict__ Bw,
                                             const float* __restrict__ bias,
                                             float* __restrict__ C)
{
    __shared__ __align__(16) char sm[4*10240];
    const uint32_t sb = smem_u32(sm);
    const int t = threadIdx.x, lane = t & 31, wid = t >> 5;
    const int wm = wid >> 1, wn = wid & 1;
    const int m0 = blockIdx.x * 128, n0 = blockIdx.y * 128;

    float c[2][8][4] = {};
    {
        #pragma unroll
        for (int i = 0; i < 2; i++) {
            int sidx = t*2 + i; int row = sidx >> 2, seg = sidx & 3;
            CP16(sb + row*80 + seg*16,           A  + (size_t)(m0+row)*KAUG + seg*8);
            CP16(sb + 20480 + row*80 + seg*16,   Bw + (size_t)(n0+row)*KAUG + seg*8);
        }
        CPC();
    }
    const uint32_t aRowOff = (uint32_t)(wm*32 + (lane&15))*80 + ((lane>>4)&1)*16;
    const uint32_t bRowOff = (uint32_t)(wn*64 + (lane&7) + ((lane>>3)&1)*8)*80
                           + ((lane>>4)&1)*16;

    for (int ch = 0; ch < 24; ch++) {
        int buf = ch & 1;
        CPW0();
        __syncthreads();
        if (ch + 1 < 24) {
            int nb = buf ^ 1;
            #pragma unroll
            for (int i = 0; i < 2; i++) {
                int sidx = t*2 + i; int row = sidx >> 2, seg = sidx & 3;
                CP16(sb + nb*10240 + row*80 + seg*16,
                     A  + (size_t)(m0+row)*KAUG + (ch+1)*32 + seg*8);
                CP16(sb + 20480 + nb*10240 + row*80 + seg*16,
                     Bw + (size_t)(n0+row)*KAUG + (ch+1)*32 + seg*8);
            }
            CPC();
        }
        uint32_t aBase = sb + buf*10240 + aRowOff;
        uint32_t bBase = sb + 20480 + buf*10240 + bRowOff;
        #pragma unroll
        for (int ks = 0; ks < 2; ks++) {
            uint32_t a0,a1,a2,a3,a4,a5,a6,a7;
            ldsm4(aBase + ks*32,            a0,a1,a2,a3);
            ldsm4(aBase + 16*80 + ks*32,    a4,a5,a6,a7);
            #pragma unroll
            for (int p = 0; p < 4; p++) {
                uint32_t b0,b1,b2,b3;
                ldsm4(bBase + p*1280 + ks*32, b0,b1,b2,b3);
                mma16816(c[0][2*p+0], a0,a1,a2,a3, b0,b2);
                mma16816(c[0][2*p+1], a0,a1,a2,a3, b1,b3);
                mma16816(c[1][2*p+0], a4,a5,a6,a7, b0,b2);
                mma16816(c[1][2*p+1], a4,a5,a6,a7, b1,b3);
            }
        }
    }
    #pragma unroll
    for (int mi = 0; mi < 2; mi++)
        #pragma unroll
        for (int ni = 0; ni < 8; ni++) {
            int row = m0 + wm*32 + mi*16 + (lane>>2);
            int col = n0 + wn*64 + ni*8 + 2*(lane&3);
            float b0v = 0.f, b1v = 0.f;
            if (BIAS) { b0v = bias[col]; b1v = bias[col+1]; }
            *(float2*)(C + (size_t)row*DD + col) =
                make_float2(c[mi][ni][0]+b0v, c[mi][ni][1]+b1v);
            *(float2*)(C + (size_t)(row+8)*DD + col) =
                make_float2(c[mi][ni][2]+b0v, c[mi][ni][3]+b1v);
        }
}

// ---------------- cheap HMMA attention (Qh.Kh only) + exact argmax patch ----
#define AQ_STRIDE  528                       // 256 half + 16B pad
#define AQS_BYTES  (128*AQ_STRIDE)           // 67584
#define AKB_OFF    AQS_BYTES
#define AKS_BYTES  (128*80)                  // one 32-col K chunk
#define MRG_OFF    (AKB_OFF + 2*AKS_BYTES)   // 88064
#define SMEM_ATTN  (MRG_OFF + 4*1024)

__global__ __launch_bounds__(256) void attn_cheap(const float* __restrict__ Qg_,
        const __half* __restrict__ Khg, const float* __restrict__ Kg_,
        const float* __restrict__ Vg_, float* __restrict__ Og_)
{
    extern __shared__ __align__(128) char smem[];
    const uint32_t sb = smem_u32(smem);
    const int t = threadIdx.x, lane = t & 31, wid = t >> 5;
    const int wm = wid >> 1, wn = wid & 1;
    const int b = blockIdx.y, q0 = blockIdx.x * 128;

    const __half* Kb = Khg + (size_t)b*NN*DD;

    // prologue prefetch: key-tile 0, chunk 0 -> buf 0 (overlaps Q build)
    {
        #pragma unroll
        for (int i = 0; i < 2; i++) {
            int sidx = t*2 + i; int row = sidx >> 2, seg = sidx & 3;
            CP16(sb + AKB_OFF + row*80 + seg*16, Kb + (size_t)row*DD + seg*8);
        }
        CPC();
    }

    // build Qh tile (pre-scaled, rounded to fp16)
    const float* Qg = Qg_ + (size_t)(b*NN + q0)*DD;
    #pragma unroll 4
    for (int i = 0; i < 32; i++) {
        int e4 = t + i*256;
        int row = e4 >> 6, c4 = e4 & 63;
        float4 v = ((const float4*)Qg)[(size_t)row*64 + c4];
        __half2 H01 = __halves2half2(__float2half_rn(v.x*SCALE_F),
                                     __float2half_rn(v.y*SCALE_F));
        __half2 H23 = __halves2half2(__float2half_rn(v.z*SCALE_F),
                                     __float2half_rn(v.w*SCALE_F));
        char* base = smem + (size_t)row*AQ_STRIDE + (size_t)c4*8;
        *(__half2*)(base)   = H01;
        *(__half2*)(base+4) = H23;
    }

    float c[2][8][4] = {};
    float rm[4], rs[4]; int ra[4];
    #pragma unroll
    for (int j = 0; j < 4; j++) { rm[j] = -3.0e38f; rs[j] = 0.f; ra[j] = 0; }

    const uint32_t aRowOff = (uint32_t)(wm*32 + (lane&15))*AQ_STRIDE + ((lane>>4)&1)*16;
    const uint32_t bRowOff = (uint32_t)(wn*64 + (lane&7) + ((lane>>3)&1)*8)*80
                           + ((lane>>4)&1)*16;

    for (int kt = 0; kt < 32; kt++) {
        for (int ch = 0; ch < 8; ch++) {
            int glob = kt*8 + ch;
            int buf = glob & 1;
            CPW0();
            __syncthreads();
            if (glob + 1 < 256) {
                int nx = glob + 1;
                int nkt = nx >> 3, nch = nx & 7, nb = buf ^ 1;
                #pragma unroll
                for (int i = 0; i < 2; i++) {
                    int sidx = t*2 + i; int row = sidx >> 2, seg = sidx & 3;
                    CP16(sb + AKB_OFF + nb*AKS_BYTES + row*80 + seg*16,
                         Kb + (size_t)(nkt*128+row)*DD + nch*32 + seg*8);
                }
                CPC();
            }
            uint32_t aBase = sb + aRowOff + (uint32_t)ch*64;
            uint32_t bBase = sb + AKB_OFF + buf*AKS_BYTES + bRowOff;
            #pragma unroll
            for (int ks = 0; ks < 2; ks++) {
                uint32_t a0,a1,a2,a3,a4,a5,a6,a7;
                ldsm4(aBase + ks*32,                  a0,a1,a2,a3);
                ldsm4(aBase + 16*AQ_STRIDE + ks*32,   a4,a5,a6,a7);
                #pragma unroll
                for (int p = 0; p < 4; p++) {
                    uint32_t b0,b1,b2,b3;
                    ldsm4(bBase + p*1280 + ks*32, b0,b1,b2,b3);
                    mma16816(c[0][2*p+0], a0,a1,a2,a3, b0,b2);
                    mma16816(c[0][2*p+1], a0,a1,a2,a3, b1,b3);
                    mma16816(c[1][2*p+0], a4,a5,a6,a7, b0,b2);
                    mma16816(c[1][2*p+1], a4,a5,a6,a7, b1,b3);
                }
            }
        }
        // per-key-tile online reduction
        #pragma unroll
        for (int j = 0; j < 4; j++) {
            int mi = j >> 1, hr = (j & 1) * 2;
            float tm = -3.0e38f; int ta = 0;
            #pragma unroll
            for (int ni = 0; ni < 8; ni++) {
                float v0 = c[mi][ni][hr], v1 = c[mi][ni][hr+1];
                int col = ni*8 + 2*(lane&3);
                if (v0 > tm) { tm = v0; ta = col; }
                if (v1 > tm) { tm = v1; ta = col+1; }
            }
            #pragma unroll
            for (int off = 1; off <= 2; off <<= 1) {
                float om = __shfl_xor_sync(0xffffffffu, tm, off);
                int   oa = __shfl_xor_sync(0xffffffffu, ta, off);
                if (om > tm || (om == tm && oa < ta)) { tm = om; ta = oa; }
            }
            float ts = 0.f;
            #pragma unroll
            for (int ni = 0; ni < 8; ni++) {
                ts += __expf(c[mi][ni][hr]   - tm);
                ts += __expf(c[mi][ni][hr+1] - tm);
            }
            #pragma unroll
            for (int off = 1; off <= 2; off <<= 1)
                ts += __shfl_xor_sync(0xffffffffu, ts, off);
            if (tm > rm[j]) {
                rs[j] = rs[j]*__expf(rm[j]-tm) + ts;
                rm[j] = tm;
                ra[j] = kt*128 + wn*64 + ta;
            } else {
                rs[j] += ts*__expf(tm - rm[j]);
            }
        }
        #pragma unroll
        for (int mi = 0; mi < 2; mi++)
            #pragma unroll
            for (int ni = 0; ni < 8; ni++)
                #pragma unroll
                for (int r = 0; r < 4; r++) c[mi][ni][r] = 0.f;
    }

    // ---- merge n-halves ----
    float* m_arr = (float*)(smem + MRG_OFF);           // [256]
    float* s_arr = (float*)(smem + MRG_OFF + 1024);    // [256]
    int*   a_arr = (int*)  (smem + MRG_OFF + 2048);    // [256]
    float* p_arr = (float*)(smem + MRG_OFF + 3072);    // [128]
    if ((lane & 3) == 0) {
        #pragma unroll
        for (int j = 0; j < 4; j++) {
            int row = wm*32 + (j>>1)*16 + (j&1)*8 + (lane>>2);
            m_arr[wn*128 + row] = rm[j];
            s_arr[wn*128 + row] = rs[j];
            a_arr[wn*128 + row] = ra[j];
        }
    }
    __syncthreads();
    if (t < 128) {
        float m0v = m_arr[t], m1v = m_arr[128+t];
        float s0  = s_arr[t], s1  = s_arr[128+t];
        float mm  = fmaxf(m0v, m1v);
        float ss  = s0*__expf(m0v-mm) + s1*__expf(m1v-mm);
        int   aa  = (m0v >= m1v) ? a_arr[t] : a_arr[128+t];
        m_arr[t] = mm; s_arr[t] = ss; a_arr[t] = aa;
    }
    __syncthreads();

    // ---- exact argmax-score patch: kills dominant softmax-sum error ----
    const float* Kb32 = Kg_ + (size_t)b*NN*DD;
    for (int rr = 0; rr < 16; rr++) {
        int row = wid*16 + rr;
        int a   = a_arr[row];
        const float* qrow = Qg  + (size_t)row*DD;
        const float* krow = Kb32 + (size_t)a*DD;
        float4 qa = ((const float4*)qrow)[lane*2], qb = ((const float4*)qrow)[lane*2+1];
        float4 ka = ((const float4*)krow)[lane*2], kb = ((const float4*)krow)[lane*2+1];
        float acc = qa.x*ka.x + qa.y*ka.y + qa.z*ka.z + qa.w*ka.w
                  + qb.x*kb.x + qb.y*kb.y + qb.z*kb.z + qb.w*kb.w;
        #pragma unroll
        for (int off = 16; off; off >>= 1)
            acc += __shfl_xor_sync(0xffffffffu, acc, off);
        if (lane == 0) {
            float sx = acc * SCALE_F;
            float Sp = s_arr[row] - 1.0f + __expf(sx - m_arr[row]);
            p_arr[row] = 1.0f / Sp;
        }
    }
    __syncthreads();

    // ---- write: keep / zero / rescue-band ----
    const float* Vb = Vg_ + (size_t)b*NN*DD;
    float*       Og = Og_ + (size_t)(b*NN + q0)*DD;
    #pragma unroll 4
    for (int i = 0; i < 32; i++) {
        int e4 = t + i*256;
        int row = e4 >> 6, c4 = e4 & 63;
        float p = p_arr[row];
        if (fabsf(p - 0.6f) < BAND) {
            if (c4 == 0) {
                int slot = atomicAdd(&g_cnt, 1);
                if (slot < MTOT) g_list[slot] = b*NN + q0 + row;
            }
            continue;   // rescue kernel writes this row
        }
        float4 o = make_float4(0.f, 0.f, 0.f, 0.f);
        if (p >= 0.6f) {
            int a = a_arr[row];
            float4 v = ((const float4*)(Vb + (size_t)a*DD))[c4];
            o = make_float4(v.x*p, v.y*p, v.z*p, v.w*p);
        }
        ((float4*)Og)[(size_t)row*64 + c4] = o;
    }
}

// ---------------- exact fp32 rescue for banded rows -------------------------
__global__ __launch_bounds__(256) void rescue(const float* __restrict__ Q,
        const float* __restrict__ K, const float* __restrict__ V,
        float* __restrict__ O)
{
    __shared__ float s_sm[4096];
    __shared__ float q_sm[256];
    __shared__ float red_m[8];
    __shared__ int   red_a[8];
    __shared__ float red_s[8];
    __shared__ float bm_sh;
    __shared__ int   ba_sh;
    const int t = threadIdx.x, lane = t & 31, w = t >> 5;
    int cnt = g_cnt; if (cnt > MTOT) cnt = MTOT;

    for (int idx = blockIdx.x; idx < cnt; idx += gridDim.x) {
        int grow = g_list[idx];
        int b = grow >> 12;
        const float* qrow = Q + (size_t)grow*DD;
        if (t < 64) ((float4*)q_sm)[t] = ((const float4*)qrow)[t];
        __syncthreads();

        const float* Kb = K + (size_t)b*NN*DD;
        float lm = -3.0e38f; int la = 0;
        for (int j = t; j < NN; j += 256) {
            const float4* kr = (const float4*)(Kb + (size_t)j*DD);
            float acc = 0.f;
            #pragma unroll
            for (int d = 0; d < 64; d++) {
                float4 kv = kr[d];
                float4 qv = ((const float4*)q_sm)[d];
                acc += qv.x*kv.x + qv.y*kv.y + qv.z*kv.z + qv.w*kv.w;
            }
            float s = acc * SCALE_F;
            s_sm[j] = s;
            if (s > lm) { lm = s; la = j; }
        }
        #pragma unroll
        for (int off = 16; off; off >>= 1) {
            float om = __shfl_xor_sync(0xffffffffu, lm, off);
            int   oa = __shfl_xor_sync(0xffffffffu, la, off);
            if (om > lm || (om == lm && oa < la)) { lm = om; la = oa; }
        }
        if (lane == 0) { red_m[w] = lm; red_a[w] = la; }
        __syncthreads();
        if (w == 0) {
            float m2 = (lane < 8) ? red_m[lane] : -3.0e38f;
            int   a2 = (lane < 8) ? red_a[lane] : 0;
            #pragma unroll
            for (int off = 4; off; off >>= 1) {
                float om = __shfl_xor_sync(0xffffffffu, m2, off);
                int   oa = __shfl_xor_sync(0xffffffffu, a2, off);
                if (om > m2 || (om == m2 && oa < a2)) { m2 = om; a2 = oa; }
            }
            if (lane == 0) { bm_sh = m2; ba_sh = a2; }
        }
        __syncthreads();
        float m = bm_sh; int amax = ba_sh;
        float ls = 0.f;
        for (int j = t; j < NN; j += 256) ls += __expf(s_sm[j] - m);
        #pragma unroll
        for (int off = 16; off; off >>= 1)
            ls += __shfl_xor_sync(0xffffffffu, ls, off);
        if (lane == 0) red_s[w] = ls;
        __syncthreads();
        if (t == 0) {
            float S = 0.f;
            #pragma unroll
            for (int i2 = 0; i2 < 8; i2++) S += red_s[i2];
            red_s[0] = 1.0f / S;
        }
        __syncthreads();
        float p = red_s[0];
        const float* vrow = V + (size_t)(b*NN + amax)*DD;
        O[(size_t)grow*DD + t] = (p >= 0.6f) ? p * vrow[t] : 0.f;
        __syncthreads();
    }
}

// ---------------------------------------------------------------------------
extern "C" void kernel_launch(void* const* d_in, const int* in_sizes, int n_in,
                              void* d_out, int out_size)
{
    const float* x  = (const float*)d_in[0];
    const float* y  = (const float*)d_in[1];
    const float* Wq = (const float*)d_in[2];
    const float* Wk = (const float*)d_in[3];
    const float* Wv = (const float*)d_in[4];
    const float* Wp = (const float*)d_in[5];
    const float* bp = (const float*)d_in[6];
    float* out = (float*)d_out;

    __half *Aaug, *Baug, *Kh, *Wt;
    float *Q, *K, *V, *Att;
    void* cntp;
    cudaGetSymbolAddress((void**)&Aaug, g_Aaug);
    cudaGetSymbolAddress((void**)&Baug, g_Baug);
    cudaGetSymbolAddress((void**)&Kh,   g_Kh);
    cudaGetSymbolAddress((void**)&Q,    g_Q);
    cudaGetSymbolAddress((void**)&K,    g_K);
    cudaGetSymbolAddress((void**)&V,    g_V);
    cudaGetSymbolAddress((void**)&Att,  g_att);
    cudaGetSymbolAddress((void**)&Wt,   g_Wt);
    cudaGetSymbolAddress(&cntp,         g_cnt);
    __half* WtQ = Wt;
    __half* WtK = Wt + (size_t)DD*KAUG;
    __half* WtV = Wt + (size_t)2*DD*KAUG;
    __half* WtP = Wt + (size_t)3*DD*KAUG;

    cudaFuncSetAttribute(attn_cheap,
                         cudaFuncAttributeMaxDynamicSharedMemorySize, SMEM_ATTN);

    cudaMemsetAsync(cntp, 0, sizeof(int));

    prep_wt4<<<dim3(256, 4), 256>>>(Wq, Wk, Wv, Wp, Wt);
    prep_aug<<<2048, 256>>>(x, Aaug);
    prep_aug<<<2048, 256>>>(y, Baug);

    dim3 gg(MTOT/128, DD/128);
    hgemm<false><<<gg, 256>>>(Aaug, WtQ, nullptr, Q);
    hgemm<false><<<gg, 256>>>(Baug, WtK, nullptr, K);
    hgemm<false><<<gg, 256>>>(Aaug, WtV, nullptr, V);

    prep_h<<<2048, 256>>>(K, Kh);

    attn_cheap<<<dim3(NN/128, BB), 256, SMEM_ATTN>>>(Q, Kh, K, V, Att);
    rescue<<<256, 256>>>(Q, K, V, Att);

    prep_aug<<<2048, 256>>>(Att, Aaug);
    hgemm<true><<<gg, 256>>>(Aaug, WtP, bp, out);
}